// round 4
// baseline (speedup 1.0000x reference)
#include <cuda_runtime.h>
#include <cuda_bf16.h>
#include <math.h>

#define N_NODES 1024
#define IN_F    256
#define OUT_F   128   // H*NH
#define TI      8     // target nodes per block

// GL in [f][j][hh] float4 layout (+1 row of f padding for branchless prefetch)
__device__ float4 GL4[33 * N_NODES];
// GR transposed rows: GRT[o][j], o = 0..127
__device__ float GRT[OUT_F * N_NODES];
// gr natural layout [j][o] for per-block gather of the 8 target rows
__device__ float GRN[N_NODES * OUT_F];

// ---------------------------------------------------------------------------
// Kernel A: block = all 256 output rows x 8 source nodes j. 512 threads.
// thread: o = t>>1 (0..255), jh = t&1, 4 j's each.
// W chunks of 32 k, register-prefetch pipeline over single smem buffer.
// ---------------------------------------------------------------------------
__global__ void __launch_bounds__(512) gat_gemm(
    const float* __restrict__ h,
    const float* __restrict__ Wl,
    const float* __restrict__ Wr)
{
    __shared__ float hs[256][8];    // [k][jj] transposed h tile (rows 32B)
    __shared__ float ws[256][33];   // W chunk [o][k'] (padded)

    const int t  = threadIdx.x;
    const int j0 = blockIdx.x * 8;
    const int o  = t >> 1;
    const int jh = t & 1;

    // load h tile transposed (coalesced over k)
    for (int idx = t; idx < 8 * 256; idx += 512) {
        int jj = idx >> 8, k = idx & 255;
        hs[k][jj] = h[(j0 + jj) * IN_F + k];
    }

    // W source row for this thread's cooperative-load slice (16 elems/chunk)
    const int lo2 = (t * 16) >> 5;        // o-row this thread loads
    const int lk2 = (t * 16) & 31;        // k offset within chunk
    const float* __restrict__ Wrow = (lo2 < 128) ? (Wl + lo2 * IN_F + lk2)
                                                 : (Wr + (lo2 - 128) * IN_F + lk2);
    float r[16];
#pragma unroll
    for (int u = 0; u < 16; u++) r[u] = Wrow[u];    // chunk 0

    float acc[4] = {0.f, 0.f, 0.f, 0.f};

    for (int c = 0; c < 8; c++) {
        __syncthreads();
#pragma unroll
        for (int u = 0; u < 16; u++) ws[lo2][lk2 + u] = r[u];
        __syncthreads();
        if (c < 7) {
            const float* wn = Wrow + (c + 1) * 32;
#pragma unroll
            for (int u = 0; u < 16; u++) r[u] = wn[u];   // prefetch next chunk
        }
        const int kc = c * 32;
#pragma unroll
        for (int k2 = 0; k2 < 32; k2++) {
            float wv = ws[o][k2];
            float4 hv = *reinterpret_cast<const float4*>(&hs[kc + k2][jh * 4]);
            acc[0] = fmaf(wv, hv.x, acc[0]);
            acc[1] = fmaf(wv, hv.y, acc[1]);
            acc[2] = fmaf(wv, hv.z, acc[2]);
            acc[3] = fmaf(wv, hv.w, acc[3]);
        }
    }

    if (o < 128) {
        // gl -> GL4[f][j][hh]
        int f = o & 31, hh = o >> 5;
#pragma unroll
        for (int u = 0; u < 4; u++) {
            int j = j0 + jh * 4 + u;
            reinterpret_cast<float*>(&GL4[f * N_NODES + j])[hh] = acc[u];
        }
    } else {
        int og = o - 128;
#pragma unroll
        for (int u = 0; u < 4; u++) {
            int j = j0 + jh * 4 + u;
            GRT[og * N_NODES + j] = acc[u];
            GRN[j * OUT_F + og]   = acc[u];
        }
    }
}

// ---------------------------------------------------------------------------
__device__ __forceinline__ float wred_sum(float v) {
#pragma unroll
    for (int d = 16; d; d >>= 1) v += __shfl_xor_sync(0xffffffffu, v, d);
    return v;
}

// ---------------------------------------------------------------------------
// Main fused kernel, per block: 8 target nodes i; thread t = source node j.
// e[i,j,h] = dotl[h](j) + dotr[i,h] + sum_f 0.4*w_f*|gl+gr|   (lrelu split)
// Softmax without max subtraction (|e| <~ 30, fp32-safe).
// ---------------------------------------------------------------------------
#define A_ROW4   1032
#define OFF_GRS  33024
#define OFF_RED  (OFF_GRS + 1024)
#define OFF_SUM  (OFF_RED + 1056)
#define OFF_DOTR (OFF_SUM + 32)
#define OFF_CW   (OFF_DOTR + 32)
#define SMEM_FLOATS (OFF_CW + 64)

__global__ void __launch_bounds__(1024, 1) gat_main(
    const int*   __restrict__ adj,
    const float* __restrict__ attn_w,
    float*       __restrict__ out)
{
    extern __shared__ float sm[];
    float4* a4     = (float4*)sm;            // 8 rows x 1032 float4
    float*  grs2   = sm + OFF_GRS;           // [o*8 + ii]
    float*  red    = sm + OFF_RED;
    float*  sumv   = sm + OFF_SUM;
    float*  dotr_s = sm + OFF_DOTR;
    float2* cw     = (float2*)(sm + OFF_CW);

    const int t    = threadIdx.x;
    const int lane = t & 31;
    const int warp = t >> 5;
    const int i0   = blockIdx.x * TI;

    if (t < 32) { float w = attn_w[t]; cw[t] = make_float2(0.6f * w, 0.4f * w); }
    { int ii = t >> 7, oo = t & 127; grs2[(oo << 3) + ii] = GRN[(i0 + ii) * OUT_F + oo]; }

    unsigned am = 0;
#pragma unroll
    for (int ii = 0; ii < TI; ii++)
        am |= (adj[(i0 + ii) * N_NODES + t] != 0) ? (1u << ii) : 0u;
    __syncthreads();

    // warp 0: dotr[ii][hh] = sum_f 0.6*w_f * gr[i0+ii][hh*32+f]
    if (t < 32) {
        int ii = t >> 2, hh = t & 3;
        float s = 0.f;
#pragma unroll 8
        for (int f = 0; f < 32; f++)
            s += cw[f].x * grs2[(((hh << 5) + f) << 3) + ii];
        dotr_s[t] = s;   // index == q = (ii<<2)+hh
    }

    // -------- Phase 1: |x| accumulation + per-thread linear part --------
    float acc[32];
#pragma unroll
    for (int q = 0; q < 32; q++) acc[q] = 0.f;
    float dotl[4] = {0.f, 0.f, 0.f, 0.f};

    const float4* grs4 = (const float4*)grs2;
    const float4* glp  = GL4 + t;
    float4 gv = glp[0];
#pragma unroll 2
    for (int f = 0; f < 32; f++) {
        float4 gvn = glp[(f + 1) * N_NODES];   // padded row at f=31
        float2 c = cw[f];
        dotl[0] = fmaf(c.x, gv.x, dotl[0]);
        dotl[1] = fmaf(c.x, gv.y, dotl[1]);
        dotl[2] = fmaf(c.x, gv.z, dotl[2]);
        dotl[3] = fmaf(c.x, gv.w, dotl[3]);
        float gl4[4] = {gv.x, gv.y, gv.z, gv.w};
#pragma unroll
        for (int hh = 0; hh < 4; hh++) {
            int o = (hh << 5) + f;
            float glv = gl4[hh];
            float4 g0 = grs4[o * 2];              // ii 0..3 (broadcast LDS.128)
            float4 g1 = grs4[o * 2 + 1];          // ii 4..7
            float x;
            x = glv + g0.x; acc[ 0 + hh] = fmaf(c.y, fabsf(x), acc[ 0 + hh]);
            x = glv + g0.y; acc[ 4 + hh] = fmaf(c.y, fabsf(x), acc[ 4 + hh]);
            x = glv + g0.z; acc[ 8 + hh] = fmaf(c.y, fabsf(x), acc[ 8 + hh]);
            x = glv + g0.w; acc[12 + hh] = fmaf(c.y, fabsf(x), acc[12 + hh]);
            x = glv + g1.x; acc[16 + hh] = fmaf(c.y, fabsf(x), acc[16 + hh]);
            x = glv + g1.y; acc[20 + hh] = fmaf(c.y, fabsf(x), acc[20 + hh]);
            x = glv + g1.z; acc[24 + hh] = fmaf(c.y, fabsf(x), acc[24 + hh]);
            x = glv + g1.w; acc[28 + hh] = fmaf(c.y, fabsf(x), acc[28 + hh]);
        }
        gv = gvn;
    }
    __syncthreads();   // dotr_s visible

    // -------- Phase 2: masked exp (no max-sub) + sum reduction --------
    {
        const float4* dr4 = (const float4*)dotr_s;
#pragma unroll
        for (int ii = 0; ii < 8; ii++) {
            float4 d = dr4[ii];
            bool m = (am >> ii) & 1u;
            int q = ii << 2;
            float e0 = acc[q + 0] + dotl[0] + d.x;
            float e1 = acc[q + 1] + dotl[1] + d.y;
            float e2 = acc[q + 2] + dotl[2] + d.z;
            float e3 = acc[q + 3] + dotl[3] + d.w;
            acc[q + 0] = m ? __expf(e0) : 0.f;
            acc[q + 1] = m ? __expf(e1) : 0.f;
            acc[q + 2] = m ? __expf(e2) : 0.f;
            acc[q + 3] = m ? __expf(e3) : 0.f;
        }
    }
    {
        int jp = t + (t >> 7);
#pragma unroll
        for (int hh = 0; hh < 4; hh++) {
            float4 v0 = make_float4(acc[ 0 + hh], acc[ 4 + hh], acc[ 8 + hh], acc[12 + hh]);
            float4 v1 = make_float4(acc[16 + hh], acc[20 + hh], acc[24 + hh], acc[28 + hh]);
            a4[(hh * 2 + 0) * A_ROW4 + jp] = v0;
            a4[(hh * 2 + 1) * A_ROW4 + jp] = v1;
        }
    }
#pragma unroll
    for (int q = 0; q < 32; q++) {
        float v = wred_sum(acc[q]);
        if (lane == 0) red[warp * 33 + q] = v;
    }
    __syncthreads();
    { int q = t >> 5; float v = red[lane * 33 + q]; v = wred_sum(v);
      if (lane == 0) sumv[q] = v; }
    __syncthreads();

    // -------- Phase 3: aggregation --------
    const int o  = t >> 3;        // output feature 0..127
    const int c  = t & 7;         // j-partition 0..7
    const int hh = o >> 5;
    float acc8[8];
#pragma unroll
    for (int ii = 0; ii < 8; ii++) acc8[ii] = 0.f;

    const float*  grow = GRT + o * N_NODES;
    const float4* r0 = a4 + (hh * 2 + 0) * A_ROW4;
    const float4* r1 = a4 + (hh * 2 + 1) * A_ROW4;
    for (int g = 0; g < 16; g++) {          // 8 jj per group; jp pad const in group
        int jb  = (g << 6) + c;
        int jp0 = jb + (g >> 1);
        const float*  gp  = grow + jb;
        const float4* p0  = r0 + jp0;
        const float4* p1  = r1 + jp0;
#pragma unroll
        for (int u = 0; u < 8; u++) {
            float grv = gp[u * 8];          // coalesced LDG, const offset
            float4 v0 = p0[u * 8];          // broadcast LDS.128, const offset
            float4 v1 = p1[u * 8];
            acc8[0] = fmaf(v0.x, grv, acc8[0]);
            acc8[1] = fmaf(v0.y, grv, acc8[1]);
            acc8[2] = fmaf(v0.z, grv, acc8[2]);
            acc8[3] = fmaf(v0.w, grv, acc8[3]);
            acc8[4] = fmaf(v1.x, grv, acc8[4]);
            acc8[5] = fmaf(v1.y, grv, acc8[5]);
            acc8[6] = fmaf(v1.z, grv, acc8[6]);
            acc8[7] = fmaf(v1.w, grv, acc8[7]);
        }
    }
    __syncthreads();               // all a_sm reads complete -> safe to reuse

    float* part = sm;              // partials [o][c][ii], stride 65 per o (padded)
#pragma unroll
    for (int ii = 0; ii < 8; ii++)
        part[o * 65 + (c << 3) + ii] = acc8[ii];
    __syncthreads();

    { int o2 = t & 127, ii2 = t >> 7;
      float s = 0.f;
#pragma unroll
      for (int c2 = 0; c2 < 8; c2++) s += part[o2 * 65 + (c2 << 3) + ii2];
      s /= sumv[(ii2 << 2) + (o2 >> 5)];
      out[(i0 + ii2) * OUT_F + o2] = (s > 0.f) ? s : expm1f(s);   // ELU
    }
}

// ---------------------------------------------------------------------------
extern "C" void kernel_launch(void* const* d_in, const int* in_sizes, int n_in,
                              void* d_out, int out_size)
{
    const float* h    = (const float*)d_in[0];
    const int*   adj  = (const int*)  d_in[1];
    const float* Wl   = (const float*)d_in[2];
    const float* Wr   = (const float*)d_in[3];
    const float* aw   = (const float*)d_in[4];
    float*       out  = (float*)d_out;

    gat_gemm<<<N_NODES / 8, 512>>>(h, Wl, Wr);

    size_t smem = SMEM_FLOATS * sizeof(float);   // ~138 KB
    cudaFuncSetAttribute(gat_main, cudaFuncAttributeMaxDynamicSharedMemorySize, (int)smem);
    gat_main<<<N_NODES / TI, 1024, smem>>>(adj, aw, out);
}

// round 5
// speedup vs baseline: 1.1204x; 1.1204x over previous
#include <cuda_runtime.h>
#include <cuda_bf16.h>
#include <math.h>

#define N_NODES 1024
#define IN_F    256
#define OUT_F   128   // H*NH
#define TI      8     // target nodes per block

// GL4[f][j] = float4 over heads (gl[j][hh*32+f], hh=0..3)
__device__ float4 GL4[32 * N_NODES];
// GRD[opair][j] = (gr[2p][j], gr[2p+1][j])
__device__ float2 GRD[64 * N_NODES];
// gr natural layout [j][o] for per-block gather of the 8 target rows
__device__ float GRN[N_NODES * OUT_F];

// ---------------------------------------------------------------------------
// Kernel A (R3 shape): grid (64 j-chunks, 2 o-halves), 256 threads.
// Block tile: 128 o x 16 j. Epilogue stages through ws for coalesced GL4 write.
// ---------------------------------------------------------------------------
__global__ void __launch_bounds__(256) gat_gemm(
    const float* __restrict__ h,
    const float* __restrict__ Wl,
    const float* __restrict__ Wr)
{
    __shared__ float hs[256][20];   // [k][jj]
    __shared__ float ws[128][33];   // W chunk [o_local][k'] / staging

    const int t  = threadIdx.x;
    const int oh = blockIdx.y;
    const int j0 = blockIdx.x * 16;
    const int ol = t & 127;
    const int jh = t >> 7;

    for (int idx = t; idx < 16 * 256; idx += 256) {
        int jj = idx >> 8, k = idx & 255;
        hs[k][jj] = h[(j0 + jj) * IN_F + k];
    }

    const float* __restrict__ W = oh ? Wr : Wl;

    float acc[8];
#pragma unroll
    for (int u = 0; u < 8; u++) acc[u] = 0.f;

    for (int kc = 0; kc < 256; kc += 32) {
        __syncthreads();
        for (int idx = t; idx < 128 * 32; idx += 256) {
            int o2 = idx >> 5, k2 = idx & 31;
            ws[o2][k2] = W[o2 * IN_F + kc + k2];
        }
        __syncthreads();
#pragma unroll
        for (int k2 = 0; k2 < 32; k2++) {
            float wv = ws[ol][k2];
            float4 a = *reinterpret_cast<const float4*>(&hs[kc + k2][jh * 8]);
            float4 b = *reinterpret_cast<const float4*>(&hs[kc + k2][jh * 8 + 4]);
            acc[0] = fmaf(wv, a.x, acc[0]);
            acc[1] = fmaf(wv, a.y, acc[1]);
            acc[2] = fmaf(wv, a.z, acc[2]);
            acc[3] = fmaf(wv, a.w, acc[3]);
            acc[4] = fmaf(wv, b.x, acc[4]);
            acc[5] = fmaf(wv, b.y, acc[5]);
            acc[6] = fmaf(wv, b.z, acc[6]);
            acc[7] = fmaf(wv, b.w, acc[7]);
        }
    }

    const int jb = jh * 8;   // local j base 0/8
    if (oh == 0) {
        // stage gl into ws[ol][j], then write GL4 coalesced as [f][j] float4
        __syncthreads();
#pragma unroll
        for (int u = 0; u < 8; u++) ws[ol][jb + u] = acc[u];
        __syncthreads();
        int f = t >> 3, jb2 = (t & 7) * 2;
        float4* gout = GL4 + (f << 10) + j0;
#pragma unroll
        for (int v = 0; v < 2; v++) {
            int j = jb2 + v;
            float4 g;
            g.x = ws[f      ][j];
            g.y = ws[32 + f ][j];
            g.z = ws[64 + f ][j];
            g.w = ws[96 + f ][j];
            gout[j] = g;
        }
    } else {
        float* grdf = (float*)GRD;
#pragma unroll
        for (int u = 0; u < 8; u++) {
            int j = j0 + jb + u;
            grdf[((ol >> 1) << 11) + (j << 1) + (ol & 1)] = acc[u];
            GRN[(j << 7) + ol] = acc[u];
        }
    }
}

// ---------------------------------------------------------------------------
__device__ __forceinline__ float wred_sum(float v) {
#pragma unroll
    for (int d = 16; d; d >>= 1) v += __shfl_xor_sync(0xffffffffu, v, d);
    return v;
}

// ---------------------------------------------------------------------------
// Main fused kernel. 1024 threads, 128 blocks (TI=8 targets each).
// Phase 1: thread = (j-pair {jj, jj+512}, ii-half ih). acc[2j][4ii][4hh].
// Phase 3: thread = (o-pair, ii-half, c-partition). acc[2o][4ii].
// ---------------------------------------------------------------------------
#define OFF_GRS  32768
#define OFF_RED  (OFF_GRS + 1024)
#define OFF_SUM  (OFF_RED + 544)
#define OFF_DOTR (OFF_SUM + 32)
#define OFF_CW   (OFF_DOTR + 32)
#define SMEM_FLOATS (OFF_CW + 64)

__global__ void __launch_bounds__(1024, 1) gat_main(
    const int*   __restrict__ adj,
    const float* __restrict__ attn_w,
    float*       __restrict__ out)
{
    extern __shared__ float sm[];
    float4* a4     = (float4*)sm;            // 8 rows x 1024 float4 (p values)
    float*  grs    = sm + OFF_GRS;           // [o][ii 0..7]
    float*  red    = sm + OFF_RED;           // 32 warps x 17
    float*  sumv   = sm + OFF_SUM;           // 32
    float*  dotr_s = sm + OFF_DOTR;          // 32
    float2* cw     = (float2*)(sm + OFF_CW);

    const int t    = threadIdx.x;
    const int lane = t & 31;
    const int warp = t >> 5;
    const int jj   = t & 511;
    const int ih   = t >> 9;                 // ii-half: 0 -> ii 0..3, 1 -> ii 4..7
    const int i0   = blockIdx.x * TI;

    if (t < 32) { float w = attn_w[t]; cw[t] = make_float2(0.6f * w, 0.4f * w); }
    { int ii = t >> 7, oo = t & 127; grs[(oo << 3) + ii] = GRN[(i0 + ii) * OUT_F + oo]; }

    unsigned am0 = 0, am1 = 0;
#pragma unroll
    for (int iil = 0; iil < 4; iil++) {
        const int* row = adj + (i0 + ih * 4 + iil) * N_NODES;
        am0 |= (row[jj]       != 0) ? (1u << iil) : 0u;
        am1 |= (row[jj + 512] != 0) ? (1u << iil) : 0u;
    }
    __syncthreads();

    // warp 0: dotr[ii][hh] = sum_f 0.6*w_f * gr[i0+ii][hh*32+f]
    if (t < 32) {
        int ii = t >> 2, hh = t & 3;
        float s = 0.f;
#pragma unroll 8
        for (int f = 0; f < 32; f++)
            s += cw[f].x * grs[(((hh << 5) + f) << 3) + ii];
        dotr_s[t] = s;   // index q = ii*4 + hh
    }

    // -------- Phase 1: |x| accumulation, 2 j-streams share each gr LDS --------
    float acc[32];               // [jsel*16 + iil*4 + hh]
#pragma unroll
    for (int q = 0; q < 32; q++) acc[q] = 0.f;
    float dl[8] = {0.f,0.f,0.f,0.f,0.f,0.f,0.f,0.f};   // [jsel*4 + hh]

    const float4* grs4 = (const float4*)grs;
#pragma unroll 2
    for (int f = 0; f < 32; f++) {
        float4 ga = GL4[(f << 10) + jj];
        float4 gb = GL4[(f << 10) + jj + 512];
        float2 c = cw[f];
        dl[0] = fmaf(c.x, ga.x, dl[0]); dl[1] = fmaf(c.x, ga.y, dl[1]);
        dl[2] = fmaf(c.x, ga.z, dl[2]); dl[3] = fmaf(c.x, ga.w, dl[3]);
        dl[4] = fmaf(c.x, gb.x, dl[4]); dl[5] = fmaf(c.x, gb.y, dl[5]);
        dl[6] = fmaf(c.x, gb.z, dl[6]); dl[7] = fmaf(c.x, gb.w, dl[7]);
        float gaa[4] = {ga.x, ga.y, ga.z, ga.w};
        float gbb[4] = {gb.x, gb.y, gb.z, gb.w};
#pragma unroll
        for (int hh = 0; hh < 4; hh++) {
            float4 g = grs4[((((hh << 5) + f) << 1)) + ih];   // 4 ii of this half
            float av = gaa[hh], bv = gbb[hh];
            float x;
            x = av + g.x; acc[ 0 + hh] = fmaf(c.y, fabsf(x), acc[ 0 + hh]);
            x = av + g.y; acc[ 4 + hh] = fmaf(c.y, fabsf(x), acc[ 4 + hh]);
            x = av + g.z; acc[ 8 + hh] = fmaf(c.y, fabsf(x), acc[ 8 + hh]);
            x = av + g.w; acc[12 + hh] = fmaf(c.y, fabsf(x), acc[12 + hh]);
            x = bv + g.x; acc[16 + hh] = fmaf(c.y, fabsf(x), acc[16 + hh]);
            x = bv + g.y; acc[20 + hh] = fmaf(c.y, fabsf(x), acc[20 + hh]);
            x = bv + g.z; acc[24 + hh] = fmaf(c.y, fabsf(x), acc[24 + hh]);
            x = bv + g.w; acc[28 + hh] = fmaf(c.y, fabsf(x), acc[28 + hh]);
        }
    }
    __syncthreads();   // dotr_s visible

    // -------- Phase 2: masked exp (no max-sub), store p, sum reduce --------
    {
        const float4* dr4 = (const float4*)dotr_s;
        float4 d0 = dr4[ih * 4 + 0], d1 = dr4[ih * 4 + 1];
        float4 d2 = dr4[ih * 4 + 2], d3 = dr4[ih * 4 + 3];
        float dra[4][4] = {{d0.x,d0.y,d0.z,d0.w},{d1.x,d1.y,d1.z,d1.w},
                           {d2.x,d2.y,d2.z,d2.w},{d3.x,d3.y,d3.z,d3.w}};
#pragma unroll
        for (int jsel = 0; jsel < 2; jsel++) {
            unsigned am = jsel ? am1 : am0;
            int jcol = jj + (jsel << 9);
#pragma unroll
            for (int hh = 0; hh < 4; hh++) {
                float ddl = dl[jsel * 4 + hh];
                int q = jsel * 16 + hh;
                float e0 = acc[q +  0] + ddl + dra[0][hh];
                float e1 = acc[q +  4] + ddl + dra[1][hh];
                float e2 = acc[q +  8] + ddl + dra[2][hh];
                float e3 = acc[q + 12] + ddl + dra[3][hh];
                float4 v;
                v.x = (am & 1u) ? __expf(e0) : 0.f;
                v.y = (am & 2u) ? __expf(e1) : 0.f;
                v.z = (am & 4u) ? __expf(e2) : 0.f;
                v.w = (am & 8u) ? __expf(e3) : 0.f;
                acc[q +  0] = v.x; acc[q +  4] = v.y;
                acc[q +  8] = v.z; acc[q + 12] = v.w;
                a4[(((hh << 1) + ih) << 10) + jcol] = v;
            }
        }
    }
#pragma unroll
    for (int ql = 0; ql < 16; ql++) {
        float v = acc[ql] + acc[16 + ql];
        v = wred_sum(v);
        if (lane == 0) red[warp * 17 + ql] = v;
    }
    __syncthreads();
    if (t < 32) {
        int ihq = t >> 4, ql = t & 15;
        float s = 0.f;
#pragma unroll
        for (int w8 = 0; w8 < 16; w8++) s += red[((ihq << 4) + w8) * 17 + ql];
        sumv[t] = s;   // sumv[ii*4 + hh] with ii = ihq*4 + (ql>>2), hh = ql&3
    }
    __syncthreads();

    // -------- Phase 3: aggregation, p LDS shared across o-pair --------
    const int opair = t >> 4;            // 0..63
    const int ihp   = (t >> 3) & 1;      // ii-half
    const int c     = t & 7;             // j-partition
    const int hh3   = opair >> 4;
    float acc8[8];
#pragma unroll
    for (int v = 0; v < 8; v++) acc8[v] = 0.f;

    const float4* prow = a4 + (((hh3 << 1) + ihp) << 10);
    const float2* grp  = GRD + (opair << 10);
#pragma unroll 4
    for (int g = 0; g < 128; g++) {
        int j = (g << 3) + c;
        float4 p  = prow[j];             // 4 ii (this half), one LDS.128
        float2 gr = grp[j];              // both o's of the pair
        acc8[0] = fmaf(p.x, gr.x, acc8[0]);
        acc8[1] = fmaf(p.y, gr.x, acc8[1]);
        acc8[2] = fmaf(p.z, gr.x, acc8[2]);
        acc8[3] = fmaf(p.w, gr.x, acc8[3]);
        acc8[4] = fmaf(p.x, gr.y, acc8[4]);
        acc8[5] = fmaf(p.y, gr.y, acc8[5]);
        acc8[6] = fmaf(p.z, gr.y, acc8[6]);
        acc8[7] = fmaf(p.w, gr.y, acc8[7]);
    }
    __syncthreads();                     // all a4 reads complete

    float* part = sm;                    // [t][8] padded to 9
#pragma unroll
    for (int v = 0; v < 8; v++) part[t * 9 + ((v >> 2) << 2) + (v & 3)] = acc8[v];
    __syncthreads();

    {
        int o2 = t & 127, ii2 = t >> 7;
        int op = o2 >> 1, oi = o2 & 1, ihq = ii2 >> 2, iil = ii2 & 3;
        float s = 0.f;
#pragma unroll
        for (int cc = 0; cc < 8; cc++)
            s += part[((op << 4) + (ihq << 3) + cc) * 9 + (oi << 2) + iil];
        s /= sumv[(ii2 << 2) + (o2 >> 5)];
        out[(i0 + ii2) * OUT_F + o2] = (s > 0.f) ? s : expm1f(s);   // ELU
    }
}

// ---------------------------------------------------------------------------
extern "C" void kernel_launch(void* const* d_in, const int* in_sizes, int n_in,
                              void* d_out, int out_size)
{
    const float* h    = (const float*)d_in[0];
    const int*   adj  = (const int*)  d_in[1];
    const float* Wl   = (const float*)d_in[2];
    const float* Wr   = (const float*)d_in[3];
    const float* aw   = (const float*)d_in[4];
    float*       out  = (float*)d_out;

    gat_gemm<<<dim3(64, 2), 256>>>(h, Wl, Wr);

    size_t smem = SMEM_FLOATS * sizeof(float);   // ~138 KB
    cudaFuncSetAttribute(gat_main, cudaFuncAttributeMaxDynamicSharedMemorySize, (int)smem);
    gat_main<<<N_NODES / TI, 1024, smem>>>(adj, aw, out);
}

// round 6
// speedup vs baseline: 1.3127x; 1.1716x over previous
#include <cuda_runtime.h>
#include <cuda_bf16.h>
#include <math.h>

#define N_NODES 1024
#define IN_F    256
#define OUT_F   128   // H*NH
#define TI      8     // target nodes per block

// GL4[f][j] = float4 over heads (gl[j][hh*32+f], hh=0..3)
__device__ float4 GL4[32 * N_NODES];
// GRD[opair][j] = (gr[2p][j], gr[2p+1][j])
__device__ float2 GRD[64 * N_NODES];
// gr natural layout [j][o] for per-block gather of the 8 target rows
__device__ float GRN[N_NODES * OUT_F];

// ---------------------------------------------------------------------------
// Packed fp32x2 helpers (Blackwell sm_103a)
// ---------------------------------------------------------------------------
__device__ __forceinline__ float2 fadd2(float2 a, float2 b) {
    float2 r;
    asm("add.rn.f32x2 %0, %1, %2;"
        : "=l"(*(unsigned long long*)&r)
        : "l"(*(const unsigned long long*)&a),
          "l"(*(const unsigned long long*)&b));
    return r;
}
__device__ __forceinline__ float2 ffma2(float2 a, float2 b, float2 c) {
    float2 r;
    asm("fma.rn.f32x2 %0, %1, %2, %3;"
        : "=l"(*(unsigned long long*)&r)
        : "l"(*(const unsigned long long*)&a),
          "l"(*(const unsigned long long*)&b),
          "l"(*(const unsigned long long*)&c));
    return r;
}
__device__ __forceinline__ float2 pack2(float x, float y) {
    float2 r;
    asm("mov.b64 %0, {%1, %2};"
        : "=l"(*(unsigned long long*)&r) : "f"(x), "f"(y));
    return r;
}

// ---------------------------------------------------------------------------
// Kernel A: grid (64 j-chunks, 2 o-halves), 512 threads.
// Entire W-half (128 rows x 256 k) + h tile (16 j x 256 k) resident in smem.
// ONE sync, then straight-line 1024-FFMA loop per thread (4 j accumulators).
// ---------------------------------------------------------------------------
#define GEMM_SMEM_FLOATS (256 * 20 + 128 * 257)

__global__ void __launch_bounds__(512) gat_gemm(
    const float* __restrict__ h,
    const float* __restrict__ Wl,
    const float* __restrict__ Wr)
{
    extern __shared__ float smg[];
    float* hsp = smg;               // [k][jj] stride 20
    float* wsp = smg + 256 * 20;    // [o][k]  stride 257

    const int t  = threadIdx.x;
    const int oh = blockIdx.y;
    const int j0 = blockIdx.x * 16;
    const int ol = t & 127;
    const int jh = t >> 7;          // 0..3
    const int jb = jh * 4;

    for (int idx = t; idx < 16 * 256; idx += 512) {
        int jj = idx >> 8, k = idx & 255;
        hsp[k * 20 + jj] = h[(j0 + jj) * IN_F + k];
    }
    const float* __restrict__ W = oh ? Wr : Wl;
    for (int idx = t; idx < 128 * 256; idx += 512) {
        int o2 = idx >> 8, k2 = idx & 255;
        wsp[o2 * 257 + k2] = W[o2 * IN_F + k2];
    }
    __syncthreads();

    float acc[4] = {0.f, 0.f, 0.f, 0.f};
#pragma unroll 8
    for (int k = 0; k < 256; k++) {
        float wv = wsp[ol * 257 + k];                     // conflict-free
        float4 hv = *reinterpret_cast<const float4*>(&hsp[k * 20 + jb]);  // broadcast
        acc[0] = fmaf(wv, hv.x, acc[0]);
        acc[1] = fmaf(wv, hv.y, acc[1]);
        acc[2] = fmaf(wv, hv.z, acc[2]);
        acc[3] = fmaf(wv, hv.w, acc[3]);
    }

    if (oh == 0) {
        // stage gl into wsp[ol][j] (stride 17), write GL4 coalesced [f][j] float4
        __syncthreads();
#pragma unroll
        for (int u = 0; u < 4; u++) wsp[ol * 17 + jb + u] = acc[u];
        __syncthreads();
        int f = t >> 4, jl = t & 15;
        float4 g;
        g.x = wsp[(f     ) * 17 + jl];
        g.y = wsp[(f + 32) * 17 + jl];
        g.z = wsp[(f + 64) * 17 + jl];
        g.w = wsp[(f + 96) * 17 + jl];
        GL4[(f << 10) + j0 + jl] = g;
    } else {
        float* grdf = (float*)GRD;
#pragma unroll
        for (int u = 0; u < 4; u++) {
            int j = j0 + jb + u;
            grdf[((ol >> 1) << 11) + (j << 1) + (ol & 1)] = acc[u];
            GRN[(j << 7) + ol] = acc[u];
        }
    }
}

// ---------------------------------------------------------------------------
__device__ __forceinline__ float wred_sum(float v) {
#pragma unroll
    for (int d = 16; d; d >>= 1) v += __shfl_xor_sync(0xffffffffu, v, d);
    return v;
}

// ---------------------------------------------------------------------------
// Main fused kernel. 1024 threads, 128 blocks (TI=8 targets each).
// Phase 1: thread = (j-pair {jj, jj+512}, ii-half ih), f32x2 adds over ii-pairs.
// Phase 3: thread = (o-pair, ii-half, c-partition), f32x2 FMAs.
// ---------------------------------------------------------------------------
#define OFF_GRS  32768
#define OFF_RED  (OFF_GRS + 1024)
#define OFF_SUM  (OFF_RED + 544)
#define OFF_DOTR (OFF_SUM + 32)
#define OFF_CW   (OFF_DOTR + 32)
#define SMEM_FLOATS (OFF_CW + 64)

__global__ void __launch_bounds__(1024, 1) gat_main(
    const int*   __restrict__ adj,
    const float* __restrict__ attn_w,
    float*       __restrict__ out)
{
    extern __shared__ float sm[];
    float4* a4     = (float4*)sm;            // 8 rows x 1024 float4 (p values)
    float*  grs    = sm + OFF_GRS;           // [o][ii 0..7]
    float*  red    = sm + OFF_RED;           // 32 warps x 17
    float*  sumv   = sm + OFF_SUM;           // 32
    float*  dotr_s = sm + OFF_DOTR;          // 32
    float2* cw     = (float2*)(sm + OFF_CW);

    const int t    = threadIdx.x;
    const int lane = t & 31;
    const int warp = t >> 5;
    const int jj   = t & 511;
    const int ih   = t >> 9;                 // ii-half: 0 -> ii 0..3, 1 -> ii 4..7
    const int i0   = blockIdx.x * TI;

    if (t < 32) { float w = attn_w[t]; cw[t] = make_float2(0.6f * w, 0.4f * w); }
    { int ii = t >> 7, oo = t & 127; grs[(oo << 3) + ii] = GRN[(i0 + ii) * OUT_F + oo]; }

    unsigned am0 = 0, am1 = 0;
#pragma unroll
    for (int iil = 0; iil < 4; iil++) {
        const int* row = adj + (i0 + ih * 4 + iil) * N_NODES;
        am0 |= (row[jj]       != 0) ? (1u << iil) : 0u;
        am1 |= (row[jj + 512] != 0) ? (1u << iil) : 0u;
    }
    __syncthreads();

    // warp 0: dotr[ii][hh] = sum_f 0.6*w_f * gr[i0+ii][hh*32+f]
    if (t < 32) {
        int ii = t >> 2, hh = t & 3;
        float s = 0.f;
#pragma unroll 8
        for (int f = 0; f < 32; f++)
            s += cw[f].x * grs[(((hh << 5) + f) << 3) + ii];
        dotr_s[t] = s;   // index q = ii*4 + hh
    }

    // -------- Phase 1: |x| accumulation (f32x2 adds), dl packed FFMA2 --------
    float acc[32];               // [jsel*16 + iil*4 + hh]
#pragma unroll
    for (int q = 0; q < 32; q++) acc[q] = 0.f;
    float2 dlp[4];               // [jsel*2 + hhpair]: (h0,h1)/(h2,h3)
#pragma unroll
    for (int q = 0; q < 4; q++) dlp[q] = make_float2(0.f, 0.f);

    const float2* grs2v = (const float2*)grs;
#pragma unroll 2
    for (int f = 0; f < 32; f++) {
        float4 ga = GL4[(f << 10) + jj];
        float4 gb = GL4[(f << 10) + jj + 512];
        float2 c = cw[f];
        float2 cx2 = pack2(c.x, c.x);
        dlp[0] = ffma2(cx2, pack2(ga.x, ga.y), dlp[0]);
        dlp[1] = ffma2(cx2, pack2(ga.z, ga.w), dlp[1]);
        dlp[2] = ffma2(cx2, pack2(gb.x, gb.y), dlp[2]);
        dlp[3] = ffma2(cx2, pack2(gb.z, gb.w), dlp[3]);
        float gaa[4] = {ga.x, ga.y, ga.z, ga.w};
        float gbb[4] = {gb.x, gb.y, gb.z, gb.w};
#pragma unroll
        for (int hh = 0; hh < 4; hh++) {
            int ob = (((hh << 5) + f) << 2) + (ih << 1);   // float2 index
            float2 g01 = grs2v[ob];                        // ii pair 0,1 of half
            float2 g23 = grs2v[ob + 1];                    // ii pair 2,3 of half
            {
                float2 gl2 = pack2(gaa[hh], gaa[hh]);
                float2 x01 = fadd2(gl2, g01);
                float2 x23 = fadd2(gl2, g23);
                acc[ 0 + hh] = fmaf(c.y, fabsf(x01.x), acc[ 0 + hh]);
                acc[ 4 + hh] = fmaf(c.y, fabsf(x01.y), acc[ 4 + hh]);
                acc[ 8 + hh] = fmaf(c.y, fabsf(x23.x), acc[ 8 + hh]);
                acc[12 + hh] = fmaf(c.y, fabsf(x23.y), acc[12 + hh]);
            }
            {
                float2 gl2 = pack2(gbb[hh], gbb[hh]);
                float2 x01 = fadd2(gl2, g01);
                float2 x23 = fadd2(gl2, g23);
                acc[16 + hh] = fmaf(c.y, fabsf(x01.x), acc[16 + hh]);
                acc[20 + hh] = fmaf(c.y, fabsf(x01.y), acc[20 + hh]);
                acc[24 + hh] = fmaf(c.y, fabsf(x23.x), acc[24 + hh]);
                acc[28 + hh] = fmaf(c.y, fabsf(x23.y), acc[28 + hh]);
            }
        }
    }
    __syncthreads();   // dotr_s visible

    // -------- Phase 2: masked exp (no max-sub), store p, sum reduce --------
    {
        float dls[8];
        dls[0] = dlp[0].x; dls[1] = dlp[0].y; dls[2] = dlp[1].x; dls[3] = dlp[1].y;
        dls[4] = dlp[2].x; dls[5] = dlp[2].y; dls[6] = dlp[3].x; dls[7] = dlp[3].y;
        const float4* dr4 = (const float4*)dotr_s;
        float4 d0 = dr4[ih * 4 + 0], d1 = dr4[ih * 4 + 1];
        float4 d2 = dr4[ih * 4 + 2], d3 = dr4[ih * 4 + 3];
        float dra[4][4] = {{d0.x,d0.y,d0.z,d0.w},{d1.x,d1.y,d1.z,d1.w},
                           {d2.x,d2.y,d2.z,d2.w},{d3.x,d3.y,d3.z,d3.w}};
#pragma unroll
        for (int jsel = 0; jsel < 2; jsel++) {
            unsigned am = jsel ? am1 : am0;
            int jcol = jj + (jsel << 9);
#pragma unroll
            for (int hh = 0; hh < 4; hh++) {
                float ddl = dls[jsel * 4 + hh];
                int q = jsel * 16 + hh;
                float e0 = acc[q +  0] + ddl + dra[0][hh];
                float e1 = acc[q +  4] + ddl + dra[1][hh];
                float e2 = acc[q +  8] + ddl + dra[2][hh];
                float e3 = acc[q + 12] + ddl + dra[3][hh];
                float4 v;
                v.x = (am & 1u) ? __expf(e0) : 0.f;
                v.y = (am & 2u) ? __expf(e1) : 0.f;
                v.z = (am & 4u) ? __expf(e2) : 0.f;
                v.w = (am & 8u) ? __expf(e3) : 0.f;
                acc[q +  0] = v.x; acc[q +  4] = v.y;
                acc[q +  8] = v.z; acc[q + 12] = v.w;
                a4[(((hh << 1) + ih) << 10) + jcol] = v;
            }
        }
    }
#pragma unroll
    for (int ql = 0; ql < 16; ql++) {
        float v = acc[ql] + acc[16 + ql];
        v = wred_sum(v);
        if (lane == 0) red[warp * 17 + ql] = v;
    }
    __syncthreads();
    if (t < 32) {
        int ihq = t >> 4, ql = t & 15;
        float s = 0.f;
#pragma unroll
        for (int w8 = 0; w8 < 16; w8++) s += red[((ihq << 4) + w8) * 17 + ql];
        sumv[t] = s;   // sumv[ii*4 + hh]
    }
    __syncthreads();

    // -------- Phase 3: aggregation with packed FMAs --------
    const int opair = t >> 4;            // 0..63
    const int ihp   = (t >> 3) & 1;      // ii-half
    const int c     = t & 7;             // j-partition
    const int hh3   = opair >> 4;
    float2 accp[4];
#pragma unroll
    for (int v = 0; v < 4; v++) accp[v] = make_float2(0.f, 0.f);

    const float4* prow = a4 + (((hh3 << 1) + ihp) << 10);
    const float2* grp  = GRD + (opair << 10);
#pragma unroll 4
    for (int g = 0; g < 128; g++) {
        int j = (g << 3) + c;
        float4 p  = prow[j];             // 4 ii (this half), one LDS.128
        float2 gr = grp[j];              // both o's of the pair
        float2 p01 = make_float2(p.x, p.y);
        float2 p23 = make_float2(p.z, p.w);
        float2 gx2 = pack2(gr.x, gr.x);
        float2 gy2 = pack2(gr.y, gr.y);
        accp[0] = ffma2(p01, gx2, accp[0]);
        accp[1] = ffma2(p23, gx2, accp[1]);
        accp[2] = ffma2(p01, gy2, accp[2]);
        accp[3] = ffma2(p23, gy2, accp[3]);
    }
    __syncthreads();                     // all a4 reads complete

    float a8[8] = {accp[0].x, accp[0].y, accp[1].x, accp[1].y,
                   accp[2].x, accp[2].y, accp[3].x, accp[3].y};
    float* part = sm;                    // [t][8] padded to 9
#pragma unroll
    for (int v = 0; v < 8; v++) part[t * 9 + ((v >> 2) << 2) + (v & 3)] = a8[v];
    __syncthreads();

    {
        int o2 = t & 127, ii2 = t >> 7;
        int op = o2 >> 1, oi = o2 & 1, ihq = ii2 >> 2, iil = ii2 & 3;
        float s = 0.f;
#pragma unroll
        for (int cc = 0; cc < 8; cc++)
            s += part[((op << 4) + (ihq << 3) + cc) * 9 + (oi << 2) + iil];
        s /= sumv[(ii2 << 2) + (o2 >> 5)];
        out[(i0 + ii2) * OUT_F + o2] = (s > 0.f) ? s : expm1f(s);   // ELU
    }
}

// ---------------------------------------------------------------------------
extern "C" void kernel_launch(void* const* d_in, const int* in_sizes, int n_in,
                              void* d_out, int out_size)
{
    const float* h    = (const float*)d_in[0];
    const int*   adj  = (const int*)  d_in[1];
    const float* Wl   = (const float*)d_in[2];
    const float* Wr   = (const float*)d_in[3];
    const float* aw   = (const float*)d_in[4];
    float*       out  = (float*)d_out;

    size_t smg = GEMM_SMEM_FLOATS * sizeof(float);   // ~149 KB
    cudaFuncSetAttribute(gat_gemm, cudaFuncAttributeMaxDynamicSharedMemorySize, (int)smg);
    gat_gemm<<<dim3(64, 2), 512, smg>>>(h, Wl, Wr);

    size_t smem = SMEM_FLOATS * sizeof(float);   // ~136 KB
    cudaFuncSetAttribute(gat_main, cudaFuncAttributeMaxDynamicSharedMemorySize, (int)smem);
    gat_main<<<N_NODES / TI, 1024, smem>>>(adj, aw, out);
}

// round 7
// speedup vs baseline: 1.3592x; 1.0354x over previous
#include <cuda_runtime.h>
#include <cuda_bf16.h>
#include <math.h>

#define N_NODES 1024
#define IN_F    256
#define OUT_F   128   // H*NH
#define TI      8     // target nodes per i-group
#define JHALF   512   // source nodes per block

// GL4[f][j] = float4 over heads (gl[j][hh*32+f], hh=0..3); row 32 = pad
__device__ float4 GL4[33 * N_NODES];
// GRD[opair][j] = (gr[2p][j], gr[2p+1][j])
__device__ float2 GRD[64 * N_NODES];
// gr natural layout [j][o]
__device__ float GRN[N_NODES * OUT_F];
// partial aggregation scratch: [iblk*2 + jhalf][ii*128 + o] and [..][ii*4+hh]
__device__ float PNUM[256][1024];
__device__ float PDEN[256][32];

// ---------------------------------------------------------------------------
// Packed fp32x2 helpers
// ---------------------------------------------------------------------------
__device__ __forceinline__ float2 fadd2(float2 a, float2 b) {
    float2 r;
    asm("add.rn.f32x2 %0, %1, %2;"
        : "=l"(*(unsigned long long*)&r)
        : "l"(*(const unsigned long long*)&a),
          "l"(*(const unsigned long long*)&b));
    return r;
}
__device__ __forceinline__ float2 ffma2(float2 a, float2 b, float2 c) {
    float2 r;
    asm("fma.rn.f32x2 %0, %1, %2, %3;"
        : "=l"(*(unsigned long long*)&r)
        : "l"(*(const unsigned long long*)&a),
          "l"(*(const unsigned long long*)&b),
          "l"(*(const unsigned long long*)&c));
    return r;
}
__device__ __forceinline__ float2 pack2(float x, float y) {
    float2 r;
    asm("mov.b64 %0, {%1, %2};"
        : "=l"(*(unsigned long long*)&r) : "f"(x), "f"(y));
    return r;
}

// ---------------------------------------------------------------------------
// Kernel A: grid (64 j-chunks, 2 o-halves), 512 threads.
// Entire W-half + h tile resident in smem; one sync, straight-line FFMA loop.
// ---------------------------------------------------------------------------
#define GEMM_SMEM_FLOATS (256 * 20 + 128 * 257)

__global__ void __launch_bounds__(512) gat_gemm(
    const float* __restrict__ h,
    const float* __restrict__ Wl,
    const float* __restrict__ Wr)
{
    extern __shared__ float smg[];
    float* hsp = smg;               // [k][jj] stride 20
    float* wsp = smg + 256 * 20;    // [o][k]  stride 257

    const int t  = threadIdx.x;
    const int oh = blockIdx.y;
    const int j0 = blockIdx.x * 16;
    const int ol = t & 127;
    const int jh = t >> 7;          // 0..3
    const int jb = jh * 4;

    for (int idx = t; idx < 16 * 256; idx += 512) {
        int jj = idx >> 8, k = idx & 255;
        hsp[k * 20 + jj] = h[(j0 + jj) * IN_F + k];
    }
    const float* __restrict__ W = oh ? Wr : Wl;
    for (int idx = t; idx < 128 * 256; idx += 512) {
        int o2 = idx >> 8, k2 = idx & 255;
        wsp[o2 * 257 + k2] = W[o2 * IN_F + k2];
    }
    __syncthreads();

    float acc[4] = {0.f, 0.f, 0.f, 0.f};
#pragma unroll 8
    for (int k = 0; k < 256; k++) {
        float wv = wsp[ol * 257 + k];
        float4 hv = *reinterpret_cast<const float4*>(&hsp[k * 20 + jb]);
        acc[0] = fmaf(wv, hv.x, acc[0]);
        acc[1] = fmaf(wv, hv.y, acc[1]);
        acc[2] = fmaf(wv, hv.z, acc[2]);
        acc[3] = fmaf(wv, hv.w, acc[3]);
    }

    if (oh == 0) {
        __syncthreads();
#pragma unroll
        for (int u = 0; u < 4; u++) wsp[ol * 17 + jb + u] = acc[u];
        __syncthreads();
        int f = t >> 4, jl = t & 15;
        float4 g;
        g.x = wsp[(f     ) * 17 + jl];
        g.y = wsp[(f + 32) * 17 + jl];
        g.z = wsp[(f + 64) * 17 + jl];
        g.w = wsp[(f + 96) * 17 + jl];
        GL4[(f << 10) + j0 + jl] = g;
    } else {
        float* grdf = (float*)GRD;
#pragma unroll
        for (int u = 0; u < 4; u++) {
            int j = j0 + jb + u;
            grdf[((ol >> 1) << 11) + (j << 1) + (ol & 1)] = acc[u];
            GRN[(j << 7) + ol] = acc[u];
        }
    }
}

// ---------------------------------------------------------------------------
// Kernel B: grid (2 j-halves, 128 i-groups), 1024 threads.
// Thread = (j, f-half); f-halves share a warp (lane halves) and combine via
// shfl.xor(16). Block emits PARTIAL num/den to global scratch (no max-pass
// softmax; partial sums compose exactly).
// ---------------------------------------------------------------------------
#define OFF_GRS  16384
#define OFF_RED  (OFF_GRS + 1024)
#define OFF_DOTR (OFF_RED + 1056)
#define OFF_CW   (OFF_DOTR + 32)
#define SMEM_FLOATS (OFF_CW + 64)

__global__ void __launch_bounds__(1024, 1) gat_main(
    const int*   __restrict__ adj,
    const float* __restrict__ attn_w,
    float*       __restrict__ out_unused)
{
    extern __shared__ float sm[];
    float4* a4     = (float4*)sm;            // 8 rows x 512 float4 (p values)
    float*  grs    = sm + OFF_GRS;           // [o][ii 0..7]
    float*  red    = sm + OFF_RED;           // 32 warps x 33
    float*  dotr_s = sm + OFF_DOTR;          // 32
    float2* cw     = (float2*)(sm + OFF_CW);

    const int t     = threadIdx.x;
    const int lane  = t & 31;
    const int warp  = t >> 5;
    const int jhb   = blockIdx.x;            // j-half
    const int ib    = blockIdx.y;            // i-group
    const int i0    = ib * TI;
    const int jbase = jhb * JHALF;
    const int jl    = lane & 15;
    const int fh    = lane >> 4;             // f-half AND ii-half role
    const int jloc  = (warp << 4) + jl;      // 0..511
    const int j     = jbase + jloc;          // global source node
    const int sidx  = ib * 2 + jhb;

    if (t < 32) { float w = attn_w[t]; cw[t] = make_float2(0.6f * w, 0.4f * w); }
    { int ii = t >> 7, oo = t & 127; grs[(oo << 3) + ii] = GRN[(i0 + ii) * OUT_F + oo]; }

    unsigned am = 0;   // 4 bits for ii in this thread's half
#pragma unroll
    for (int iil = 0; iil < 4; iil++)
        am |= (adj[(i0 + (fh << 2) + iil) * N_NODES + j] != 0) ? (1u << iil) : 0u;
    __syncthreads();

    // warp 0: dotr[ii][hh] = sum_f 0.6*w_f * gr[i0+ii][hh*32+f]
    if (t < 32) {
        int ii = t >> 2, hh = t & 3;
        float s = 0.f;
#pragma unroll 8
        for (int f = 0; f < 32; f++)
            s += cw[f].x * grs[(((hh << 5) + f) << 3) + ii];
        dotr_s[t] = s;   // index q = ii*4 + hh
    }

    // -------- Phase 1: half the f's per thread, all 8 ii --------
    float acc[32];               // [ii*4 + hh]
#pragma unroll
    for (int q = 0; q < 32; q++) acc[q] = 0.f;
    float dl[4] = {0.f, 0.f, 0.f, 0.f};

    const float4* grs4 = (const float4*)grs;
    const int fbase = fh << 4;
    for (int fi = 0; fi < 16; fi++) {
        int f = fbase + fi;
        float4 ga = GL4[(f << 10) + j];
        float2 c = cw[f];
        dl[0] = fmaf(c.x, ga.x, dl[0]);
        dl[1] = fmaf(c.x, ga.y, dl[1]);
        dl[2] = fmaf(c.x, ga.z, dl[2]);
        dl[3] = fmaf(c.x, ga.w, dl[3]);
        float gaa[4] = {ga.x, ga.y, ga.z, ga.w};
#pragma unroll
        for (int hh = 0; hh < 4; hh++) {
            int o = (hh << 5) + f;
            float4 g0 = grs4[o * 2];         // ii 0..3
            float4 g1 = grs4[o * 2 + 1];     // ii 4..7
            float2 gl2 = pack2(gaa[hh], gaa[hh]);
            float2 x01 = fadd2(gl2, pack2(g0.x, g0.y));
            float2 x23 = fadd2(gl2, pack2(g0.z, g0.w));
            float2 x45 = fadd2(gl2, pack2(g1.x, g1.y));
            float2 x67 = fadd2(gl2, pack2(g1.z, g1.w));
            acc[ 0 + hh] = fmaf(c.y, fabsf(x01.x), acc[ 0 + hh]);
            acc[ 4 + hh] = fmaf(c.y, fabsf(x01.y), acc[ 4 + hh]);
            acc[ 8 + hh] = fmaf(c.y, fabsf(x23.x), acc[ 8 + hh]);
            acc[12 + hh] = fmaf(c.y, fabsf(x23.y), acc[12 + hh]);
            acc[16 + hh] = fmaf(c.y, fabsf(x45.x), acc[16 + hh]);
            acc[20 + hh] = fmaf(c.y, fabsf(x45.y), acc[20 + hh]);
            acc[24 + hh] = fmaf(c.y, fabsf(x67.x), acc[24 + hh]);
            acc[28 + hh] = fmaf(c.y, fabsf(x67.y), acc[28 + hh]);
        }
    }
    // combine f-halves: lane l <-> l^16 hold the two partial sums for same j
#pragma unroll
    for (int q = 0; q < 32; q++) acc[q] += __shfl_xor_sync(0xffffffffu, acc[q], 16);
#pragma unroll
    for (int hh = 0; hh < 4; hh++) dl[hh] += __shfl_xor_sync(0xffffffffu, dl[hh], 16);
    __syncthreads();   // dotr_s visible

    // -------- Phase 2: each lane-half finalizes its 4 ii --------
    float p[16];       // [iil*4 + hh], ii = fh*4 + iil
    {
        const int qb = fh << 4;
#pragma unroll
        for (int iil = 0; iil < 4; iil++) {
            bool m = (am >> iil) & 1u;
#pragma unroll
            for (int hh = 0; hh < 4; hh++) {
                float e = acc[qb + iil * 4 + hh] + dl[hh]
                        + dotr_s[(((fh << 2) + iil) << 2) + hh];
                p[iil * 4 + hh] = m ? __expf(e) : 0.f;
            }
        }
        // store p: row = hh*2 + fh, float4 over iil
#pragma unroll
        for (int hh = 0; hh < 4; hh++) {
            float4 v = make_float4(p[hh], p[4 + hh], p[8 + hh], p[12 + hh]);
            a4[(((hh << 1) + fh) << 9) + jloc] = v;
        }
    }
    // partial den: reduce over 16 j within each half-warp
#pragma unroll
    for (int qq = 0; qq < 16; qq++) {
        float v = p[qq];
#pragma unroll
        for (int d = 8; d; d >>= 1) v += __shfl_xor_sync(0xffffffffu, v, d);
        if (jl == 0) red[warp * 33 + (fh << 4) + qq] = v;   // q = ii*4+hh ordering: (fh*4+iil)*4+hh = fh*16 + qq ✓
    }
    __syncthreads();   // p stores + red complete
    if (t < 32) {
        float s = 0.f;
#pragma unroll
        for (int w8 = 0; w8 < 32; w8++) s += red[w8 * 33 + t];
        PDEN[sidx][t] = s;     // q = ii*4 + hh
    }

    // -------- Phase 3: partial aggregation over this j-half --------
    const int opair = t >> 4;            // 0..63
    const int ihp   = (t >> 3) & 1;      // ii-half
    const int c     = t & 7;             // j-partition
    const int hh3   = opair >> 4;
    float2 accp[4];
#pragma unroll
    for (int v = 0; v < 4; v++) accp[v] = make_float2(0.f, 0.f);

    const float4* prow = a4 + (((hh3 << 1) + ihp) << 9);
    const float2* grp  = GRD + (opair << 10) + jbase;
#pragma unroll 4
    for (int g = 0; g < 64; g++) {
        int jl3 = (g << 3) + c;
        float4 pv = prow[jl3];           // 4 ii of this half
        float2 gr = grp[jl3];            // both o's of the pair
        float2 p01 = make_float2(pv.x, pv.y);
        float2 p23 = make_float2(pv.z, pv.w);
        float2 gx2 = pack2(gr.x, gr.x);
        float2 gy2 = pack2(gr.y, gr.y);
        accp[0] = ffma2(p01, gx2, accp[0]);
        accp[1] = ffma2(p23, gx2, accp[1]);
        accp[2] = ffma2(p01, gy2, accp[2]);
        accp[3] = ffma2(p23, gy2, accp[3]);
    }
    __syncthreads();                     // all a4 reads complete

    float a8[8] = {accp[0].x, accp[0].y, accp[1].x, accp[1].y,
                   accp[2].x, accp[2].y, accp[3].x, accp[3].y};
    float* part = sm;                    // [t][8] padded to 9
#pragma unroll
    for (int v = 0; v < 8; v++) part[t * 9 + v] = a8[v];
    __syncthreads();

    {
        int o2 = t & 127, ii2 = t >> 7;
        int op = o2 >> 1, oi = o2 & 1, ihq = ii2 >> 2, iil = ii2 & 3;
        float s = 0.f;
#pragma unroll
        for (int cc = 0; cc < 8; cc++)
            s += part[((op << 4) + (ihq << 3) + cc) * 9 + (oi << 2) + iil];
        PNUM[sidx][(ii2 << 7) + o2] = s;
    }
}

// ---------------------------------------------------------------------------
// Kernel C: combine the two j-half partials, normalize, ELU, write out.
// ---------------------------------------------------------------------------
__global__ void __launch_bounds__(1024) gat_combine(float* __restrict__ out)
{
    const int b = blockIdx.x;            // i-group
    const int t = threadIdx.x;
    const int ii2 = t >> 7, o2 = t & 127;
    float num = PNUM[b * 2][t] + PNUM[b * 2 + 1][t];
    int q = (ii2 << 2) + (o2 >> 5);
    float den = PDEN[b * 2][q] + PDEN[b * 2 + 1][q];
    float s = num / den;
    out[(b * TI + ii2) * OUT_F + o2] = (s > 0.f) ? s : expm1f(s);
}

// ---------------------------------------------------------------------------
extern "C" void kernel_launch(void* const* d_in, const int* in_sizes, int n_in,
                              void* d_out, int out_size)
{
    const float* h    = (const float*)d_in[0];
    const int*   adj  = (const int*)  d_in[1];
    const float* Wl   = (const float*)d_in[2];
    const float* Wr   = (const float*)d_in[3];
    const float* aw   = (const float*)d_in[4];
    float*       out  = (float*)d_out;

    size_t smg = GEMM_SMEM_FLOATS * sizeof(float);   // ~149 KB
    cudaFuncSetAttribute(gat_gemm, cudaFuncAttributeMaxDynamicSharedMemorySize, (int)smg);
    gat_gemm<<<dim3(64, 2), 512, smg>>>(h, Wl, Wr);

    size_t smem = SMEM_FLOATS * sizeof(float);       // ~74 KB
    cudaFuncSetAttribute(gat_main, cudaFuncAttributeMaxDynamicSharedMemorySize, (int)smem);
    gat_main<<<dim3(2, N_NODES / TI), 1024, smem>>>(adj, aw, out);

    gat_combine<<<N_NODES / TI, 1024>>>(out);
}

// round 9
// speedup vs baseline: 1.4018x; 1.0314x over previous
#include <cuda_runtime.h>
#include <cuda_bf16.h>
#include <math.h>

#define N_NODES 1024
#define IN_F    256
#define OUT_F   128   // H*NH
#define TI      8     // target nodes per i-group
#define JHALF   512   // source nodes per block

// GL4[f][j] = float4 over heads (gl[j][hh*32+f], hh=0..3); row 32 = pad
__device__ float4 GL4[33 * N_NODES];
// GRD[opair][j] = (gr[2p][j], gr[2p+1][j])
__device__ float2 GRD[64 * N_NODES];
// gr natural layout [j][o]
__device__ float GRN[N_NODES * OUT_F];
// partial aggregation scratch
__device__ float PNUM[256][1024];
__device__ float PDEN[256][32];

// ---------------------------------------------------------------------------
// Packed fp32x2 helpers
// ---------------------------------------------------------------------------
__device__ __forceinline__ float2 fadd2(float2 a, float2 b) {
    float2 r;
    asm("add.rn.f32x2 %0, %1, %2;"
        : "=l"(*(unsigned long long*)&r)
        : "l"(*(const unsigned long long*)&a),
          "l"(*(const unsigned long long*)&b));
    return r;
}
__device__ __forceinline__ float2 ffma2(float2 a, float2 b, float2 c) {
    float2 r;
    asm("fma.rn.f32x2 %0, %1, %2, %3;"
        : "=l"(*(unsigned long long*)&r)
        : "l"(*(const unsigned long long*)&a),
          "l"(*(const unsigned long long*)&b),
          "l"(*(const unsigned long long*)&c));
    return r;
}
__device__ __forceinline__ float2 pack2(float x, float y) {
    float2 r;
    asm("mov.b64 %0, {%1, %2};"
        : "=l"(*(unsigned long long*)&r) : "f"(x), "f"(y));
    return r;
}

// ---------------------------------------------------------------------------
// Kernel A: tiled GEMM. grid (16 j-chunks, 8 o-groups), 256 threads.
// Tile = 64 j x 32 o-slots, k chunks of 64, register double-buffered.
// o-groups 0..3 -> gl (8 f x 4 hh per block, W rows permuted at load);
// o-groups 4..7 -> gr (32 consecutive og).
// ---------------------------------------------------------------------------
#define HS_STRIDE 68
#define WS_STRIDE 34
#define SS 69

__global__ void __launch_bounds__(256) gat_gemm(
    const float* __restrict__ h,
    const float* __restrict__ Wl,
    const float* __restrict__ Wr)
{
    __shared__ float hs[64 * HS_STRIDE];   // [k][j_loc]
    __shared__ float ws[64 * WS_STRIDE];   // [k][o_slot]

    const int t  = threadIdx.x;
    const int bx = blockIdx.x;             // j-chunk
    const int by = blockIdx.y;             // o-group
    const int j0 = bx * 64;
    const bool is_gl = (by < 4);

    // compute-role indices
    const int po = t & 15;                 // o-pair: slots {2po, 2po+1}
    const int jq = t >> 4;                 // j-quad: j_loc 4jq..4jq+3

    // load-role indices
    const int ls  = t >> 3;                // W slot (0..31)
    const int lkg = (t & 7) * 8;           // W k-offset (8 floats)
    const int ljl = t >> 2;                // h j (0..63)
    const int lkh = (t & 3) * 16;          // h k-offset (16 floats)

    // W row for slot ls
    int wrow;
    const float* __restrict__ Wsrc;
    if (is_gl) { wrow = ((ls >> 3) << 5) + (by << 3) + (ls & 7); Wsrc = Wl; }
    else       { wrow = ((by - 4) << 5) + ls;                    Wsrc = Wr; }
    const float* __restrict__ wptr = Wsrc + wrow * IN_F + lkg;
    const float* __restrict__ hptr = h + (j0 + ljl) * IN_F + lkh;

    float rw[8], rh[16];
#pragma unroll
    for (int u = 0; u < 2; u++) *(float4*)&rw[u * 4] = *(const float4*)&wptr[u * 4];
#pragma unroll
    for (int u = 0; u < 4; u++) *(float4*)&rh[u * 4] = *(const float4*)&hptr[u * 4];

    float2 accp[4];
#pragma unroll
    for (int v = 0; v < 4; v++) accp[v] = make_float2(0.f, 0.f);

    for (int c = 0; c < 4; c++) {
        __syncthreads();
#pragma unroll
        for (int u = 0; u < 8; u++)  ws[(lkg + u) * WS_STRIDE + ls]  = rw[u];
#pragma unroll
        for (int u = 0; u < 16; u++) hs[(lkh + u) * HS_STRIDE + ljl] = rh[u];
        __syncthreads();
        if (c < 3) {
            const float* wn = wptr + (c + 1) * 64;
            const float* hn = hptr + (c + 1) * 64;
#pragma unroll
            for (int u = 0; u < 2; u++) *(float4*)&rw[u * 4] = *(const float4*)&wn[u * 4];
#pragma unroll
            for (int u = 0; u < 4; u++) *(float4*)&rh[u * 4] = *(const float4*)&hn[u * 4];
        }
#pragma unroll 8
        for (int k = 0; k < 64; k++) {
            float2 wv = *(const float2*)&ws[k * WS_STRIDE + 2 * po];
            float4 hv = *(const float4*)&hs[k * HS_STRIDE + 4 * jq];
            accp[0] = ffma2(pack2(hv.x, hv.x), wv, accp[0]);
            accp[1] = ffma2(pack2(hv.y, hv.y), wv, accp[1]);
            accp[2] = ffma2(pack2(hv.z, hv.z), wv, accp[2]);
            accp[3] = ffma2(pack2(hv.w, hv.w), wv, accp[3]);
        }
    }

    if (is_gl) {
        // stage [slot][j_loc] then emit GL4 float4 over hh (coalesced)
        __syncthreads();
#pragma unroll
        for (int v = 0; v < 4; v++) {
            hs[(2 * po    ) * SS + 4 * jq + v] = (&accp[v].x)[0];
            hs[(2 * po + 1) * SS + 4 * jq + v] = (&accp[v].x)[1];
        }
        __syncthreads();
        const int fl = t >> 5, jl = t & 31;      // fl 0..7
        const int f  = (by << 3) + fl;
#pragma unroll
        for (int half = 0; half < 2; half++) {
            int jc = jl + half * 32;
            float4 g;
            g.x = hs[( 0 + fl) * SS + jc];
            g.y = hs[( 8 + fl) * SS + jc];
            g.z = hs[(16 + fl) * SS + jc];
            g.w = hs[(24 + fl) * SS + jc];
            GL4[(f << 10) + j0 + jc] = g;
        }
    } else {
        // direct writes: GRN coalesced STG.64, GRD pair rows, GRN/GRD share accp
        const int og0 = (by - 4) << 5;
        const int pg  = (og0 >> 1) + po;     // global o-pair
#pragma unroll
        for (int v = 0; v < 4; v++) {
            int j = j0 + 4 * jq + v;
            *(float2*)&GRN[(j << 7) + og0 + 2 * po] = accp[v];
            GRD[(pg << 10) + j] = accp[v];
        }
    }
}

// ---------------------------------------------------------------------------
// Kernel B: grid (2 j-halves, 128 i-groups), 1024 threads.
// Thread = (j, f-half); f-halves share a warp (lane halves) and combine via
// shfl.xor(16). Block emits PARTIAL num/den to global scratch (no max-pass
// softmax; partial sums compose exactly).
// ---------------------------------------------------------------------------
#define OFF_GRS  16384
#define OFF_RED  (OFF_GRS + 1024)
#define OFF_DOTR (OFF_RED + 1056)
#define OFF_CW   (OFF_DOTR + 32)
#define SMEM_FLOATS (OFF_CW + 64)

__global__ void __launch_bounds__(1024, 1) gat_main(
    const int*   __restrict__ adj,
    const float* __restrict__ attn_w,
    float*       __restrict__ out_unused)
{
    extern __shared__ float sm[];
    float4* a4     = (float4*)sm;            // 8 rows x 512 float4 (p values)
    float*  grs    = sm + OFF_GRS;           // [o][ii 0..7]
    float*  red    = sm + OFF_RED;           // 32 warps x 33
    float*  dotr_s = sm + OFF_DOTR;          // 32
    float2* cw     = (float2*)(sm + OFF_CW);

    const int t     = threadIdx.x;
    const int lane  = t & 31;
    const int warp  = t >> 5;
    const int jhb   = blockIdx.x;            // j-half
    const int ib    = blockIdx.y;            // i-group
    const int i0    = ib * TI;
    const int jbase = jhb * JHALF;
    const int jl    = lane & 15;
    const int fh    = lane >> 4;             // f-half AND ii-half role
    const int jloc  = (warp << 4) + jl;      // 0..511
    const int j     = jbase + jloc;          // global source node
    const int sidx  = ib * 2 + jhb;

    if (t < 32) { float w = attn_w[t]; cw[t] = make_float2(0.6f * w, 0.4f * w); }
    { int ii = t >> 7, oo = t & 127; grs[(oo << 3) + ii] = GRN[(i0 + ii) * OUT_F + oo]; }

    unsigned am = 0;   // 4 bits for ii in this thread's half
#pragma unroll
    for (int iil = 0; iil < 4; iil++)
        am |= (adj[(i0 + (fh << 2) + iil) * N_NODES + j] != 0) ? (1u << iil) : 0u;
    __syncthreads();

    // warp 0: dotr[ii][hh] = sum_f 0.6*w_f * gr[i0+ii][hh*32+f]
    if (t < 32) {
        int ii = t >> 2, hh = t & 3;
        float s = 0.f;
#pragma unroll 8
        for (int f = 0; f < 32; f++)
            s += cw[f].x * grs[(((hh << 5) + f) << 3) + ii];
        dotr_s[t] = s;   // index q = ii*4 + hh
    }

    // -------- Phase 1: half the f's per thread, all 8 ii --------
    float acc[32];               // [ii*4 + hh]
#pragma unroll
    for (int q = 0; q < 32; q++) acc[q] = 0.f;
    float dl[4] = {0.f, 0.f, 0.f, 0.f};

    const float4* grs4 = (const float4*)grs;
    const int fbase = fh << 4;
    for (int fi = 0; fi < 16; fi++) {
        int f = fbase + fi;
        float4 ga = GL4[(f << 10) + j];
        float2 c = cw[f];
        dl[0] = fmaf(c.x, ga.x, dl[0]);
        dl[1] = fmaf(c.x, ga.y, dl[1]);
        dl[2] = fmaf(c.x, ga.z, dl[2]);
        dl[3] = fmaf(c.x, ga.w, dl[3]);
        float gaa[4] = {ga.x, ga.y, ga.z, ga.w};
#pragma unroll
        for (int hh = 0; hh < 4; hh++) {
            int o = (hh << 5) + f;
            float4 g0 = grs4[o * 2];         // ii 0..3
            float4 g1 = grs4[o * 2 + 1];     // ii 4..7
            float2 gl2 = pack2(gaa[hh], gaa[hh]);
            float2 x01 = fadd2(gl2, pack2(g0.x, g0.y));
            float2 x23 = fadd2(gl2, pack2(g0.z, g0.w));
            float2 x45 = fadd2(gl2, pack2(g1.x, g1.y));
            float2 x67 = fadd2(gl2, pack2(g1.z, g1.w));
            acc[ 0 + hh] = fmaf(c.y, fabsf(x01.x), acc[ 0 + hh]);
            acc[ 4 + hh] = fmaf(c.y, fabsf(x01.y), acc[ 4 + hh]);
            acc[ 8 + hh] = fmaf(c.y, fabsf(x23.x), acc[ 8 + hh]);
            acc[12 + hh] = fmaf(c.y, fabsf(x23.y), acc[12 + hh]);
            acc[16 + hh] = fmaf(c.y, fabsf(x45.x), acc[16 + hh]);
            acc[20 + hh] = fmaf(c.y, fabsf(x45.y), acc[20 + hh]);
            acc[24 + hh] = fmaf(c.y, fabsf(x67.x), acc[24 + hh]);
            acc[28 + hh] = fmaf(c.y, fabsf(x67.y), acc[28 + hh]);
        }
    }
    // combine f-halves: lane l <-> l^16 hold the two partial sums for same j
#pragma unroll
    for (int q = 0; q < 32; q++) acc[q] += __shfl_xor_sync(0xffffffffu, acc[q], 16);
#pragma unroll
    for (int hh = 0; hh < 4; hh++) dl[hh] += __shfl_xor_sync(0xffffffffu, dl[hh], 16);
    __syncthreads();   // dotr_s visible

    // -------- Phase 2: each lane-half finalizes its 4 ii --------
    float p[16];       // [iil*4 + hh], ii = fh*4 + iil
    {
        const int qb = fh << 4;
#pragma unroll
        for (int iil = 0; iil < 4; iil++) {
            bool m = (am >> iil) & 1u;
#pragma unroll
            for (int hh = 0; hh < 4; hh++) {
                float e = acc[qb + iil * 4 + hh] + dl[hh]
                        + dotr_s[(((fh << 2) + iil) << 2) + hh];
                p[iil * 4 + hh] = m ? __expf(e) : 0.f;
            }
        }
        // store p: row = hh*2 + fh, float4 over iil
#pragma unroll
        for (int hh = 0; hh < 4; hh++) {
            float4 v = make_float4(p[hh], p[4 + hh], p[8 + hh], p[12 + hh]);
            a4[(((hh << 1) + fh) << 9) + jloc] = v;
        }
    }
    // partial den: reduce over 16 j within each half-warp
#pragma unroll
    for (int qq = 0; qq < 16; qq++) {
        float v = p[qq];
#pragma unroll
        for (int d = 8; d; d >>= 1) v += __shfl_xor_sync(0xffffffffu, v, d);
        if (jl == 0) red[warp * 33 + (fh << 4) + qq] = v;
    }
    __syncthreads();   // p stores + red complete
    if (t < 32) {
        float s = 0.f;
#pragma unroll
        for (int w8 = 0; w8 < 32; w8++) s += red[w8 * 33 + t];
        PDEN[sidx][t] = s;     // q = ii*4 + hh
    }

    // -------- Phase 3: partial aggregation over this j-half --------
    const int opair = t >> 4;            // 0..63
    const int ihp   = (t >> 3) & 1;      // ii-half
    const int c     = t & 7;             // j-partition
    const int hh3   = opair >> 4;
    float2 accp[4];
#pragma unroll
    for (int v = 0; v < 4; v++) accp[v] = make_float2(0.f, 0.f);

    const float4* prow = a4 + (((hh3 << 1) + ihp) << 9);
    const float2* grp  = GRD + (opair << 10) + jbase;
#pragma unroll 4
    for (int g = 0; g < 64; g++) {
        int jl3 = (g << 3) + c;
        float4 pv = prow[jl3];           // 4 ii of this half
        float2 gr = grp[jl3];            // both o's of the pair
        float2 p01 = make_float2(pv.x, pv.y);
        float2 p23 = make_float2(pv.z, pv.w);
        float2 gx2 = pack2(gr.x, gr.x);
        float2 gy2 = pack2(gr.y, gr.y);
        accp[0] = ffma2(p01, gx2, accp[0]);
        accp[1] = ffma2(p23, gx2, accp[1]);
        accp[2] = ffma2(p01, gy2, accp[2]);
        accp[3] = ffma2(p23, gy2, accp[3]);
    }
    __syncthreads();                     // all a4 reads complete

    float a8[8] = {accp[0].x, accp[0].y, accp[1].x, accp[1].y,
                   accp[2].x, accp[2].y, accp[3].x, accp[3].y};
    float* part = sm;                    // [t][8] padded to 9
#pragma unroll
    for (int v = 0; v < 8; v++) part[t * 9 + v] = a8[v];
    __syncthreads();

    {
        int o2 = t & 127, ii2 = t >> 7;
        int op = o2 >> 1, oi = o2 & 1, ihq = ii2 >> 2, iil = ii2 & 3;
        float s = 0.f;
#pragma unroll
        for (int cc = 0; cc < 8; cc++)
            s += part[((op << 4) + (ihq << 3) + cc) * 9 + (oi << 2) + iil];
        PNUM[sidx][(ii2 << 7) + o2] = s;
    }
}

// ---------------------------------------------------------------------------
// Kernel C: combine the two j-half partials, normalize, ELU, write out.
// ---------------------------------------------------------------------------
__global__ void __launch_bounds__(1024) gat_combine(float* __restrict__ out)
{
    const int b = blockIdx.x;            // i-group
    const int t = threadIdx.x;
    const int ii2 = t >> 7, o2 = t & 127;
    float num = PNUM[b * 2][t] + PNUM[b * 2 + 1][t];
    int q = (ii2 << 2) + (o2 >> 5);
    float den = PDEN[b * 2][q] + PDEN[b * 2 + 1][q];
    float s = num / den;
    out[(b * TI + ii2) * OUT_F + o2] = (s > 0.f) ? s : expm1f(s);
}

// ---------------------------------------------------------------------------
extern "C" void kernel_launch(void* const* d_in, const int* in_sizes, int n_in,
                              void* d_out, int out_size)
{
    const float* h    = (const float*)d_in[0];
    const int*   adj  = (const int*)  d_in[1];
    const float* Wl   = (const float*)d_in[2];
    const float* Wr   = (const float*)d_in[3];
    const float* aw   = (const float*)d_in[4];
    float*       out  = (float*)d_out;

    gat_gemm<<<dim3(16, 8), 256>>>(h, Wl, Wr);

    size_t smem = SMEM_FLOATS * sizeof(float);       // ~74 KB
    cudaFuncSetAttribute(gat_main, cudaFuncAttributeMaxDynamicSharedMemorySize, (int)smem);
    gat_main<<<dim3(2, N_NODES / TI), 1024, smem>>>(adj, aw, out);

    gat_combine<<<N_NODES / TI, 1024>>>(out);
}